// round 11
// baseline (speedup 1.0000x reference)
#include <cuda_runtime.h>
#include <stdint.h>

typedef unsigned long long ull;

#define TOKENS 16384
#define DIM    256
#define KW     8192

#define BM     128
#define BN     128
#define BK     32
#define SPLIT  16
#define NRANGE (KW / SPLIT)             // 512 codes per CTA
#define STAGES ((NRANGE / BN) * (DIM / BK))   // 4 * 8 = 32
#define XROWF  128                       // x tile row width (floats)
#define WROWF  256                       // w-dup tile row width (floats)
#define XTILEB (BK * XROWF * 4)          // 16384
#define WTILEB (BK * WROWF * 4)          // 32768
#define BUFB   (XTILEB + WTILEB)         // 49152
#define NBUF   2
#define SMEM_BYTES (NBUF * BUFB)         // 98304 -> 2 CTAs/SM

__device__ float g_wn[KW];
__device__ float g_pval[TOKENS * SPLIT];
__device__ int   g_pidx[TOKENS * SPLIT];
__device__ float g_xT[(size_t)DIM * TOKENS];      // [d][token]
__device__ float g_wT2[(size_t)DIM * 2 * KW];     // [d][2*code], duplicated pairs

// ---------------- helpers ----------------
__device__ __forceinline__ uint32_t smem_u32(const void* p) {
    uint32_t a;
    asm("{ .reg .u64 t; cvta.to.shared.u64 t, %1; cvt.u32.u64 %0, t; }" : "=r"(a) : "l"(p));
    return a;
}
#define CP_ASYNC16(dst, src) \
    asm volatile("cp.async.cg.shared.global [%0], [%1], 16;" :: "r"(dst), "l"(src) : "memory")

// ---------------- prepass ----------------
// x transpose: src [rows][256] -> dst [256][rows]
__global__ void transpose_kernel(const float* __restrict__ src, float* __restrict__ dst,
                                 int rows) {
    __shared__ float t[32][33];
    const int c0 = blockIdx.x * 32;
    const int r0 = blockIdx.y * 32;
#pragma unroll
    for (int i = 0; i < 4; i++)
        t[threadIdx.y + 8 * i][threadIdx.x] =
            src[(size_t)(r0 + threadIdx.y + 8 * i) * DIM + c0 + threadIdx.x];
    __syncthreads();
#pragma unroll
    for (int i = 0; i < 4; i++)
        dst[(size_t)(c0 + threadIdx.y + 8 * i) * rows + r0 + threadIdx.x] =
            t[threadIdx.x][threadIdx.y + 8 * i];
}

// w dup-transpose: src [KW][256] -> dst [256][2*KW], each value at 2c and 2c+1
__global__ void dup_transpose_kernel(const float* __restrict__ src, float* __restrict__ dst) {
    __shared__ float t[32][33];
    const int c0 = blockIdx.x * 32;   // dim
    const int r0 = blockIdx.y * 32;   // code
#pragma unroll
    for (int i = 0; i < 4; i++)
        t[threadIdx.y + 8 * i][threadIdx.x] =
            src[(size_t)(r0 + threadIdx.y + 8 * i) * DIM + c0 + threadIdx.x];
    __syncthreads();
#pragma unroll
    for (int i = 0; i < 4; i++) {
        const int d = c0 + threadIdx.y + 8 * i;
        const int c = r0 + threadIdx.x;
        const float v = t[threadIdx.x][threadIdx.y + 8 * i];
        float2 vv = make_float2(v, v);
        *(float2*)(dst + (size_t)d * (2 * KW) + 2 * c) = vv;
    }
}

__global__ void wnorm_kernel(const float* __restrict__ w) {
    int k = blockIdx.x * 256 + threadIdx.x;
    const float4* row = (const float4*)(w + (size_t)k * DIM);
    float s = 0.f;
#pragma unroll
    for (int i = 0; i < DIM / 4; i++) {
        float4 v = row[i];
        s += v.x * v.x + v.y * v.y + v.z * v.z + v.w * v.w;
    }
    g_wn[k] = s;
}

// ---------------- main FFMA2 kernel ----------------
// grid (TOKENS/BM, SPLIT) = (128, 16) = 2048 CTAs; block 128 threads
// tx = tid&15 (8 codes: tx+16j), ty = tid>>4 (16 tokens: ty*16..+15)
extern __shared__ char dynsmem[];

__device__ __forceinline__ void load_stage(uint32_t sbase, int gs, int tid,
                                           int mbase, int nbase0) {
    if (gs < STAGES) {
        const int buf = gs & 1;
        const int dt = (gs & 7) * BK;
        const int nb2 = 2 * (nbase0 + (gs >> 3) * BN);
        const uint32_t xb = sbase + buf * BUFB;
        const uint32_t wb = xb + XTILEB;
        // x tile: 32 rows x 512B = 1024 chunks
#pragma unroll
        for (int i = 0; i < 8; i++) {
            const int idx = tid + 128 * i;
            const int row = idx >> 5, col = idx & 31;
            CP_ASYNC16(xb + row * (XROWF * 4) + col * 16,
                       g_xT + (size_t)(dt + row) * TOKENS + mbase + col * 4);
        }
        // w-dup tile: 32 rows x 1024B = 2048 chunks
#pragma unroll
        for (int i = 0; i < 16; i++) {
            const int idx = tid + 128 * i;
            const int row = idx >> 6, col = idx & 63;
            CP_ASYNC16(wb + row * (WROWF * 4) + col * 16,
                       g_wT2 + (size_t)(dt + row) * (2 * KW) + nb2 + col * 4);
        }
    }
    asm volatile("cp.async.commit_group;" ::: "memory");
}

__global__ __launch_bounds__(128, 2)
void vq_ffma_kernel() {
    char* sm = dynsmem;
    const uint32_t sbase = smem_u32(sm);
    const int tid = threadIdx.x;
    const int tx = tid & 15;
    const int ty = tid >> 4;
    const int mbase = blockIdx.x * BM;
    const int nbase0 = blockIdx.y * NRANGE;

    ull acc[8][8];
#pragma unroll
    for (int p = 0; p < 8; p++)
#pragma unroll
        for (int j = 0; j < 8; j++) acc[p][j] = 0ull;

    float bv[16];
    int   bi[16];
#pragma unroll
    for (int t = 0; t < 16; t++) { bv[t] = -3.402823e38f; bi[t] = 0x7fffffff; }

    load_stage(sbase, 0, tid, mbase, nbase0);

    for (int gs = 0; gs < STAGES; gs++) {
        load_stage(sbase, gs + 1, tid, mbase, nbase0);       // commits even if empty
        asm volatile("cp.async.wait_group 1;" ::: "memory"); // stage gs resident
        __syncthreads();

        const char* bufp = sm + (gs & 1) * BUFB;
        const float* xsp = (const float*)bufp;
        const float* wsp = (const float*)(bufp + XTILEB);

#pragma unroll
        for (int k = 0; k < BK; k++) {
            const ulonglong2* xrow = (const ulonglong2*)(xsp + k * XROWF + ty * 16);
            ulonglong2 xq0 = xrow[0];
            ulonglong2 xq1 = xrow[1];
            ulonglong2 xq2 = xrow[2];
            ulonglong2 xq3 = xrow[3];
            const ull* wrow = (const ull*)(wsp + k * WROWF) + tx;   // dup pairs, stride 16 ull
            ull w2[8];
#pragma unroll
            for (int j = 0; j < 8; j++) w2[j] = wrow[16 * j];
#pragma unroll
            for (int j = 0; j < 8; j++) {
                asm("fma.rn.f32x2 %0, %1, %2, %0;" : "+l"(acc[0][j]) : "l"(xq0.x), "l"(w2[j]));
                asm("fma.rn.f32x2 %0, %1, %2, %0;" : "+l"(acc[1][j]) : "l"(xq0.y), "l"(w2[j]));
                asm("fma.rn.f32x2 %0, %1, %2, %0;" : "+l"(acc[2][j]) : "l"(xq1.x), "l"(w2[j]));
                asm("fma.rn.f32x2 %0, %1, %2, %0;" : "+l"(acc[3][j]) : "l"(xq1.y), "l"(w2[j]));
                asm("fma.rn.f32x2 %0, %1, %2, %0;" : "+l"(acc[4][j]) : "l"(xq2.x), "l"(w2[j]));
                asm("fma.rn.f32x2 %0, %1, %2, %0;" : "+l"(acc[5][j]) : "l"(xq2.y), "l"(w2[j]));
                asm("fma.rn.f32x2 %0, %1, %2, %0;" : "+l"(acc[6][j]) : "l"(xq3.x), "l"(w2[j]));
                asm("fma.rn.f32x2 %0, %1, %2, %0;" : "+l"(acc[7][j]) : "l"(xq3.y), "l"(w2[j]));
            }
        }

        if ((gs & 7) == 7) {
            const int nb = nbase0 + (gs >> 3) * BN;
#pragma unroll
            for (int j = 0; j < 8; j++) {
                const int n = nb + tx + 16 * j;
                const float wn = __ldg(&g_wn[n]);
#pragma unroll
                for (int p = 0; p < 8; p++) {
                    float lo, hi;
                    asm("mov.b64 {%0, %1}, %2;" : "=f"(lo), "=f"(hi) : "l"(acc[p][j]));
                    const float s0 = wn - 2.f * lo;
                    const float s1 = wn - 2.f * hi;
                    const int t0 = 2 * p, t1 = 2 * p + 1;
                    if (s0 > bv[t0] || (s0 == bv[t0] && n < bi[t0])) { bv[t0] = s0; bi[t0] = n; }
                    if (s1 > bv[t1] || (s1 == bv[t1] && n < bi[t1])) { bv[t1] = s1; bi[t1] = n; }
                    acc[p][j] = 0ull;
                }
            }
        }
        __syncthreads();   // buffer gs&1 fully consumed before next prefetch overwrites it
    }

    // reduce across the 16 tx lanes
#pragma unroll
    for (int off = 8; off >= 1; off >>= 1) {
#pragma unroll
        for (int t = 0; t < 16; t++) {
            float ov = __shfl_xor_sync(0xffffffffu, bv[t], off);
            int   oi = __shfl_xor_sync(0xffffffffu, bi[t], off);
            if (ov > bv[t] || (ov == bv[t] && oi < bi[t])) { bv[t] = ov; bi[t] = oi; }
        }
    }

    if (tx == 0) {
        const int s = blockIdx.y;
#pragma unroll
        for (int t = 0; t < 16; t++) {
            const int tok = mbase + ty * 16 + t;
            g_pval[tok * SPLIT + s] = bv[t];
            g_pidx[tok * SPLIT + s] = bi[t];
        }
    }
}

// ---------------- combine split partials + gather ----------------
__global__ void reduce_gather_kernel(const float* __restrict__ wt, float* __restrict__ out) {
    const int tok = blockIdx.x;
    float bv = -3.402823e38f;
    int   bi = 0x7fffffff;
#pragma unroll
    for (int s = 0; s < SPLIT; s++) {
        const float v = g_pval[tok * SPLIT + s];
        const int   i = g_pidx[tok * SPLIT + s];
        if (v > bv || (v == bv && i < bi)) { bv = v; bi = i; }
    }
    const float4 v = *(const float4*)(wt + (size_t)bi * DIM + threadIdx.x * 4);
    *(float4*)(out + (size_t)tok * DIM + threadIdx.x * 4) = v;
}

// ---------------- launch ----------------
extern "C" void kernel_launch(void* const* d_in, const int* in_sizes, int n_in,
                              void* d_out, int out_size) {
    const float* x  = (const float*)d_in[0];   // [16384, 256]
    const float* wt = (const float*)d_in[1];   // [8192, 256]
    float* out = (float*)d_out;

    cudaFuncSetAttribute(vq_ffma_kernel, cudaFuncAttributeMaxDynamicSharedMemorySize, SMEM_BYTES);

    {
        float* xT = 0;
        cudaGetSymbolAddress((void**)&xT, g_xT);
        float* wT2 = 0;
        cudaGetSymbolAddress((void**)&wT2, g_wT2);
        dim3 bt(32, 8);
        transpose_kernel<<<dim3(DIM / 32, TOKENS / 32), bt>>>(x, xT, TOKENS);
        dup_transpose_kernel<<<dim3(DIM / 32, KW / 32), bt>>>(wt, wT2);
        wnorm_kernel<<<KW / 256, 256>>>(wt);
    }

    dim3 grid(TOKENS / BM, SPLIT);
    vq_ffma_kernel<<<grid, 128, SMEM_BYTES>>>();

    reduce_gather_kernel<<<TOKENS, 64>>>(wt, out);
}

// round 12
// speedup vs baseline: 1.0591x; 1.0591x over previous
#include <cuda_runtime.h>
#include <stdint.h>

typedef unsigned long long ull;

#define TOKENS 16384
#define DIM    256
#define KW     8192

#define BM     128
#define BN     128
#define BK     32
#define SPLIT  16
#define NRANGE (KW / SPLIT)             // 512 codes per CTA
#define STAGES ((NRANGE / BN) * (DIM / BK))   // 4 * 8 = 32
#define SW     128                       // smem row width (floats)
#define TILEB  (BK * SW * 4)             // 16384 bytes per tile
#define BUFB   (2 * TILEB)               // 32768
#define NBUF   3
#define SMEM_BYTES (NBUF * BUFB)         // 98304 -> 2 CTAs/SM

__device__ float g_wn[KW];
__device__ float g_pval[TOKENS * SPLIT];
__device__ int   g_pidx[TOKENS * SPLIT];
__device__ float g_xT[(size_t)DIM * TOKENS];   // [d][token]
__device__ float g_wT[(size_t)DIM * KW];       // [d][code]

// ---------------- helpers ----------------
__device__ __forceinline__ uint32_t smem_u32(const void* p) {
    uint32_t a;
    asm("{ .reg .u64 t; cvta.to.shared.u64 t, %1; cvt.u32.u64 %0, t; }" : "=r"(a) : "l"(p));
    return a;
}
#define CP_ASYNC16(dst, src) \
    asm volatile("cp.async.cg.shared.global [%0], [%1], 16;" :: "r"(dst), "l"(src) : "memory")

// ---------------- prepass: transpose + weight norms ----------------
__global__ void transpose_kernel(const float* __restrict__ src, float* __restrict__ dst,
                                 int rows) {
    __shared__ float t[32][33];
    const int c0 = blockIdx.x * 32;
    const int r0 = blockIdx.y * 32;
#pragma unroll
    for (int i = 0; i < 4; i++)
        t[threadIdx.y + 8 * i][threadIdx.x] =
            src[(size_t)(r0 + threadIdx.y + 8 * i) * DIM + c0 + threadIdx.x];
    __syncthreads();
#pragma unroll
    for (int i = 0; i < 4; i++)
        dst[(size_t)(c0 + threadIdx.y + 8 * i) * rows + r0 + threadIdx.x] =
            t[threadIdx.x][threadIdx.y + 8 * i];
}

__global__ void wnorm_kernel(const float* __restrict__ w) {
    int k = blockIdx.x * 256 + threadIdx.x;
    const float4* row = (const float4*)(w + (size_t)k * DIM);
    float s = 0.f;
#pragma unroll
    for (int i = 0; i < DIM / 4; i++) {
        float4 v = row[i];
        s += v.x * v.x + v.y * v.y + v.z * v.z + v.w * v.w;
    }
    g_wn[k] = s;
}

// ---------------- main FFMA2 kernel ----------------
// grid (TOKENS/BM, SPLIT) = (128, 16); block 256 threads
// tx = tid&15 (8 codes: tx+16j), ty = tid>>4 (16 groups x 8 tokens)
// thread tile: 8 tokens (4 f32x2 pairs) x 8 codes = 32 packed accumulators
extern __shared__ char dynsmem[];

__device__ __forceinline__ void load_stage(uint32_t sbase, int gs, int tid,
                                           int mbase, int nbase0) {
    if (gs < STAGES) {
        const int buf = gs % NBUF;
        const int dt = (gs & 7) * BK;
        const int nb = nbase0 + (gs >> 3) * BN;
        const uint32_t xb = sbase + buf * BUFB;
        const uint32_t wb = xb + TILEB;
#pragma unroll
        for (int i = 0; i < 4; i++) {
            const int idx = tid + 256 * i;        // 0..1023
            const int row = idx >> 5;             // 0..31 (k within stage)
            const int col = idx & 31;             // 16B chunk
            CP_ASYNC16(xb + row * (SW * 4) + col * 16,
                       g_xT + (size_t)(dt + row) * TOKENS + mbase + col * 4);
            CP_ASYNC16(wb + row * (SW * 4) + col * 16,
                       g_wT + (size_t)(dt + row) * KW + nb + col * 4);
        }
    }
    asm volatile("cp.async.commit_group;" ::: "memory");
}

__global__ __launch_bounds__(256, 2)
void vq_ffma_kernel() {
    char* sm = dynsmem;
    const uint32_t sbase = smem_u32(sm);
    const int tid = threadIdx.x;
    const int tx = tid & 15;
    const int ty = tid >> 4;
    const int mbase = blockIdx.x * BM;
    const int nbase0 = blockIdx.y * NRANGE;

    ull acc[4][8];
#pragma unroll
    for (int p = 0; p < 4; p++)
#pragma unroll
        for (int j = 0; j < 8; j++) acc[p][j] = 0ull;

    float bv[8];
    int   bi[8];
#pragma unroll
    for (int t = 0; t < 8; t++) { bv[t] = -3.402823e38f; bi[t] = 0x7fffffff; }

    load_stage(sbase, 0, tid, mbase, nbase0);

    for (int gs = 0; gs < STAGES; gs++) {
        load_stage(sbase, gs + 1, tid, mbase, nbase0);       // commits even if empty
        asm volatile("cp.async.wait_group 1;" ::: "memory"); // stage gs resident
        __syncthreads();

        const float* xsp = (const float*)(sm + (gs % NBUF) * BUFB);
        const float* wsp = (const float*)(sm + (gs % NBUF) * BUFB + TILEB);

#pragma unroll
        for (int k = 0; k < BK; k++) {
            const ulonglong2* xrow = (const ulonglong2*)(xsp + k * SW + ty * 8);
            ulonglong2 xq0 = xrow[0];                       // tokens 0-3 (2 pairs)
            ulonglong2 xq1 = xrow[1];                       // tokens 4-7
            ull w2[8];
#pragma unroll
            for (int j = 0; j < 8; j++) {
                float wv = wsp[k * SW + tx + 16 * j];
                asm("mov.b64 %0, {%1, %1};" : "=l"(w2[j]) : "f"(wv));
            }
#pragma unroll
            for (int j = 0; j < 8; j++) {
                asm("fma.rn.f32x2 %0, %1, %2, %0;" : "+l"(acc[0][j]) : "l"(xq0.x), "l"(w2[j]));
                asm("fma.rn.f32x2 %0, %1, %2, %0;" : "+l"(acc[1][j]) : "l"(xq0.y), "l"(w2[j]));
                asm("fma.rn.f32x2 %0, %1, %2, %0;" : "+l"(acc[2][j]) : "l"(xq1.x), "l"(w2[j]));
                asm("fma.rn.f32x2 %0, %1, %2, %0;" : "+l"(acc[3][j]) : "l"(xq1.y), "l"(w2[j]));
            }
        }

        if ((gs & 7) == 7) {
            // chunk epilogue: score = ||w||^2 - 2 x.w ; streaming argmax
            const int nb = nbase0 + (gs >> 3) * BN;
#pragma unroll
            for (int j = 0; j < 8; j++) {
                const int n = nb + tx + 16 * j;
                const float wn = __ldg(&g_wn[n]);
#pragma unroll
                for (int p = 0; p < 4; p++) {
                    float lo, hi;
                    asm("mov.b64 {%0, %1}, %2;" : "=f"(lo), "=f"(hi) : "l"(acc[p][j]));
                    const float s0 = wn - 2.f * lo;
                    const float s1 = wn - 2.f * hi;
                    const int t0 = 2 * p, t1 = 2 * p + 1;
                    if (s0 > bv[t0] || (s0 == bv[t0] && n < bi[t0])) { bv[t0] = s0; bi[t0] = n; }
                    if (s1 > bv[t1] || (s1 == bv[t1] && n < bi[t1])) { bv[t1] = s1; bi[t1] = n; }
                    acc[p][j] = 0ull;
                }
            }
        }
    }

    // reduce across the 16 tx lanes (xor stays within 16-lane halves; ty preserved)
#pragma unroll
    for (int off = 8; off >= 1; off >>= 1) {
#pragma unroll
        for (int t = 0; t < 8; t++) {
            float ov = __shfl_xor_sync(0xffffffffu, bv[t], off);
            int   oi = __shfl_xor_sync(0xffffffffu, bi[t], off);
            if (ov > bv[t] || (ov == bv[t] && oi < bi[t])) { bv[t] = ov; bi[t] = oi; }
        }
    }

    if (tx == 0) {
        const int s = blockIdx.y;
#pragma unroll
        for (int t = 0; t < 8; t++) {
            const int tok = mbase + ty * 8 + t;
            g_pval[tok * SPLIT + s] = bv[t];
            g_pidx[tok * SPLIT + s] = bi[t];
        }
    }
}

// ---------------- combine split partials + gather ----------------
__global__ void reduce_gather_kernel(const float* __restrict__ wt, float* __restrict__ out) {
    const int tok = blockIdx.x;
    float bv = -3.402823e38f;
    int   bi = 0x7fffffff;
#pragma unroll
    for (int s = 0; s < SPLIT; s++) {
        const float v = g_pval[tok * SPLIT + s];
        const int   i = g_pidx[tok * SPLIT + s];
        if (v > bv || (v == bv && i < bi)) { bv = v; bi = i; }
    }
    const float4 v = *(const float4*)(wt + (size_t)bi * DIM + threadIdx.x * 4);
    *(float4*)(out + (size_t)tok * DIM + threadIdx.x * 4) = v;
}

// ---------------- launch ----------------
extern "C" void kernel_launch(void* const* d_in, const int* in_sizes, int n_in,
                              void* d_out, int out_size) {
    const float* x  = (const float*)d_in[0];   // [16384, 256]
    const float* wt = (const float*)d_in[1];   // [8192, 256]
    float* out = (float*)d_out;

    cudaFuncSetAttribute(vq_ffma_kernel, cudaFuncAttributeMaxDynamicSharedMemorySize, SMEM_BYTES);

    {
        float* xT = 0; float* wT = 0;
        cudaGetSymbolAddress((void**)&xT, g_xT);
        cudaGetSymbolAddress((void**)&wT, g_wT);
        dim3 bt(32, 8);
        transpose_kernel<<<dim3(DIM / 32, TOKENS / 32), bt>>>(x, xT, TOKENS);
        transpose_kernel<<<dim3(DIM / 32, KW / 32), bt>>>(wt, wT, KW);
        wnorm_kernel<<<KW / 256, 256>>>(wt);
    }

    dim3 grid(TOKENS / BM, SPLIT);
    vq_ffma_kernel<<<grid, 256, SMEM_BYTES>>>();

    reduce_gather_kernel<<<TOKENS, 64>>>(wt, out);
}